// round 5
// baseline (speedup 1.0000x reference)
#include <cuda_runtime.h>

// LossMIDU: mean over 4-connected components of the tanh(x)>0 mask of
//   sum(tanh(x) in comp) / (N+1 - count(comp)).
// Run-based union-find CCL with bitmask merge, MUFU tanh, root-list compaction.

static constexpr int E      = 4096;
static constexpr int NPIX   = E * E;
static constexpr int WORDS  = NPIX / 32;
static constexpr int WPR    = E / 32;          // words per row = 128
static constexpr int MAXR   = NPIX / 2;        // max possible components

__device__ int      g_parent[NPIX];
__device__ float    g_sum[NPIX];
__device__ int      g_cnt[NPIX];
__device__ unsigned g_mask[WORDS];
__device__ int      g_roots[MAXR];
__device__ int      g_nroots;
__device__ double   g_total;
__device__ unsigned g_done;

// tanh for v > 0 via MUFU: tanh(v) = (1 - e)/(1 + e), e = exp(-2v).
__device__ __forceinline__ float tanh_pos(float v) {
    float e = __expf(-2.0f * v);               // (0, 1]
    return __fdividef(1.0f - e, 1.0f + e);
}

// Path-halving find. Links always point to strictly smaller indices.
__device__ __forceinline__ int find_root(int i) {
    int p = g_parent[i];
    if (p == i) return i;
    while (true) {
        int gp = g_parent[p];
        if (gp == p) return p;
        g_parent[i] = gp;   // path halving (monotone toward root, race-safe)
        i = p;
        p = gp;
    }
}

__device__ __forceinline__ void unite(int a, int b) {
    int ra = find_root(a);
    int rb = find_root(b);
    while (ra != rb) {
        if (ra > rb) { int t = ra; ra = rb; rb = t; }
        int old = atomicCAS(&g_parent[rb], rb, ra);
        if (old == rb) return;
        rb = find_root(old);
    }
}

// parent[i] = horizontal run start via warp max-scan over 128-pixel windows
// (windows never span rows). Also emits the bitmask and zeroes scratch.
__global__ void k_init(const float* __restrict__ x) {
    int chunk = blockIdx.x * blockDim.x + threadIdx.x;
    int base  = chunk << 2;
    float4 xv = reinterpret_cast<const float4*>(x)[chunk];
    float v[4] = {xv.x, xv.y, xv.z, xv.w};
    unsigned m = 0;
    #pragma unroll
    for (int j = 0; j < 4; j++) m |= (unsigned)(v[j] > 0.0f) << j;

    __shared__ unsigned char s_nib[256];
    s_nib[threadIdx.x] = (unsigned char)m;

    int lane  = threadIdx.x & 31;
    int wbase = base - (lane << 2);            // 128-aligned window base
    unsigned zeros = (~m) & 0xFu;
    int lz = zeros ? (base + 31 - __clz(zeros)) : (wbase - 1);

    int incl = lz;
    #pragma unroll
    for (int off = 1; off < 32; off <<= 1) {
        int t = __shfl_up_sync(0xffffffffu, incl, off);
        if (lane >= off) incl = max(incl, t);
    }
    int excl = __shfl_up_sync(0xffffffffu, incl, 1);
    if (lane == 0) excl = wbase - 1;

    int p[4];
    int prevz = excl;
    #pragma unroll
    for (int j = 0; j < 4; j++) {
        int i = base + j;
        if ((m >> j) & 1u) {
            int pj = prevz + 1;
            if (i == wbase && (i & (E - 1)) != 0 && x[i - 1] > 0.0f) pj = i - 1;
            p[j] = pj;
        } else {
            p[j] = i;
            prevz = i;
        }
    }
    reinterpret_cast<int4*>(g_parent)[chunk] = make_int4(p[0], p[1], p[2], p[3]);
    reinterpret_cast<float4*>(g_sum)[chunk]  = make_float4(0.f, 0.f, 0.f, 0.f);
    reinterpret_cast<int4*>(g_cnt)[chunk]    = make_int4(0, 0, 0, 0);

    __syncthreads();
    if (threadIdx.x < 32) {
        unsigned w = 0;
        #pragma unroll
        for (int k = 0; k < 8; k++)
            w |= (unsigned)s_nib[threadIdx.x * 8 + k] << (4 * k);
        g_mask[blockIdx.x * 32 + threadIdx.x] = w;
    }
    if (chunk == 0) { g_total = 0.0; g_done = 0u; g_nroots = 0; }
}

// Vertical unions from mask words: one block per row (rows 1..E-1),
// one 32-pixel word per thread. Union once per overlap-run start.
__global__ void __launch_bounds__(WPR) k_merge() {
    int row  = blockIdx.x + 1;
    int wcol = threadIdx.x;
    int widx = row * WPR + wcol;
    unsigned wc = g_mask[widx];
    unsigned wu = g_mask[widx - WPR];
    unsigned ov = wc & wu;
    if (!ov) return;

    int lane = threadIdx.x & 31;
    unsigned cl = __shfl_up_sync(0xffffffffu, wc, 1);
    unsigned ul = __shfl_up_sync(0xffffffffu, wu, 1);
    unsigned carry = 0;
    if (wcol > 0) {
        if (lane == 0) {
            cl = g_mask[widx - 1];
            ul = g_mask[widx - 1 - WPR];
        }
        carry = (cl >> 31) & (ul >> 31) & 1u;
    }
    unsigned starts = ov & ~((ov << 1) | carry);

    int base = row * E + (wcol << 5);
    while (starts) {
        int b = __ffs(starts) - 1;
        starts &= starts - 1;
        unite(base + b, base + b - E);
    }
}

// One find + two atomics per horizontal run; first toucher records the root.
__global__ void k_accum(const float* __restrict__ x) {
    int chunk = blockIdx.x * blockDim.x + threadIdx.x;
    int base  = chunk << 2;
    float4 xv = reinterpret_cast<const float4*>(x)[chunk];
    float v[4] = {xv.x, xv.y, xv.z, xv.w};
    int lane    = threadIdx.x & 31;
    float lw    = __shfl_up_sync(0xffffffffu, xv.w, 1);
    int colbase = base & (E - 1);
    float left0;
    if (colbase == 0)   left0 = -1.0f;
    else if (lane > 0)  left0 = lw;
    else                left0 = x[base - 1];

    #pragma unroll
    for (int j = 0; j < 4; j++) {
        float lv = j ? v[j-1] : left0;
        if (v[j] > 0.0f && lv <= 0.0f) {
            int   i   = base + j;
            int   col = colbase + j;
            float s   = 0.0f;
            int   len = 0;
            float cur = v[j];
            while (true) {
                s += tanh_pos(cur);
                len++;
                if (col + len >= E) break;
                cur = (j + len < 4) ? v[j + len] : x[i + len];
                if (cur <= 0.0f) break;
            }
            int r = find_root(i);
            int old = atomicAdd(&g_cnt[r], len);
            if (old == 0)
                g_roots[atomicAdd(&g_nroots, 1)] = r;
            atomicAdd(&g_sum[r], s);
        }
    }
}

// Grid-stride gather over the compact root list; block-reduce; last block writes.
__global__ void k_final(float* __restrict__ out) {
    int n      = g_nroots;
    int stride = gridDim.x * blockDim.x;
    const float np1 = (float)(NPIX + 1);
    double t = 0.0;
    for (int i = blockIdx.x * blockDim.x + threadIdx.x; i < n; i += stride) {
        int   r   = g_roots[i];
        int   cnt = g_cnt[r];
        float s   = g_sum[r];
        float denom = np1 - (float)cnt;        // fp32 like reference
        t += (double)(s / denom);
    }
    #pragma unroll
    for (int off = 16; off; off >>= 1)
        t += __shfl_down_sync(0xffffffffu, t, off);
    __shared__ double st[8];
    int lane = threadIdx.x & 31;
    int w    = threadIdx.x >> 5;
    if (lane == 0) st[w] = t;
    __syncthreads();
    if (w == 0) {
        int nw = blockDim.x >> 5;
        t = (lane < nw) ? st[lane] : 0.0;
        #pragma unroll
        for (int off = 4; off; off >>= 1)
            t += __shfl_down_sync(0xffffffffu, t, off);
        if (lane == 0) {
            atomicAdd(&g_total, t);
            __threadfence();
            unsigned ticket = atomicAdd(&g_done, 1u);
            if (ticket == gridDim.x - 1) {
                double tt = *((volatile double*)&g_total);
                out[0] = (n > 0) ? (float)(tt / (double)n) : 0.0f;
            }
        }
    }
}

extern "C" void kernel_launch(void* const* d_in, const int* in_sizes, int n_in,
                              void* d_out, int out_size) {
    const float* x   = (const float*)d_in[0];
    float*       out = (float*)d_out;

    const int threads    = 256;
    const int chunks_all = NPIX / 4;

    k_init <<<chunks_all / threads, threads>>>(x);
    k_merge<<<E - 1, WPR>>>();
    k_accum<<<chunks_all / threads, threads>>>(x);
    k_final<<<2048, threads>>>(out);
}

// round 7
// speedup vs baseline: 3.4492x; 3.4492x over previous
#include <cuda_runtime.h>

// LossMIDU: mean over 4-connected components of the tanh(x)>0 mask of
//   sum(tanh(x) in comp) / (N+1 - count(comp)).
// Run-based union-find CCL with bitmask merge + MUFU tanh.
//   k_init : parent[i] = horizontal run start (warp scan) + mask bits + zero scratch
//   k_merge: vertical CAS unions from mask words, one per overlap-run start
//   k_accum: one find + 2 non-returning atomics per horizontal run
//   k_final: cnt-gated vectorized root scan, block reduce, last block writes out

static constexpr int E      = 4096;
static constexpr int NPIX   = E * E;
static constexpr int WORDS  = NPIX / 32;
static constexpr int WPR    = E / 32;          // words per row = 128

__device__ int      g_parent[NPIX];
__device__ float    g_sum[NPIX];
__device__ int      g_cnt[NPIX];
__device__ unsigned g_mask[WORDS];
__device__ double   g_total;
__device__ double   g_ncomp;
__device__ unsigned g_done;

// tanh for v > 0 via MUFU: tanh(v) = (1 - e)/(1 + e), e = exp(-2v).
// Verified rel_err 0.0 vs reference in round 5.
__device__ __forceinline__ float tanh_pos(float v) {
    float e = __expf(-2.0f * v);               // (0, 1]
    return __fdividef(1.0f - e, 1.0f + e);
}

// Path-halving find. Links always point to strictly smaller indices.
__device__ __forceinline__ int find_root(int i) {
    int p = g_parent[i];
    if (p == i) return i;
    while (true) {
        int gp = g_parent[p];
        if (gp == p) return p;
        g_parent[i] = gp;   // path halving (monotone toward root, race-safe)
        i = p;
        p = gp;
    }
}

__device__ __forceinline__ void unite(int a, int b) {
    int ra = find_root(a);
    int rb = find_root(b);
    while (ra != rb) {
        if (ra > rb) { int t = ra; ra = rb; rb = t; }
        int old = atomicCAS(&g_parent[rb], rb, ra);
        if (old == rb) return;
        rb = find_root(old);
    }
}

// parent[i] = horizontal run start via warp max-scan over 128-pixel windows
// (windows never span rows). Also emits the bitmask and zeroes scratch.
__global__ void k_init(const float* __restrict__ x) {
    int chunk = blockIdx.x * blockDim.x + threadIdx.x;
    int base  = chunk << 2;
    float4 xv = reinterpret_cast<const float4*>(x)[chunk];
    float v[4] = {xv.x, xv.y, xv.z, xv.w};
    unsigned m = 0;
    #pragma unroll
    for (int j = 0; j < 4; j++) m |= (unsigned)(v[j] > 0.0f) << j;

    __shared__ unsigned char s_nib[256];
    s_nib[threadIdx.x] = (unsigned char)m;

    int lane  = threadIdx.x & 31;
    int wbase = base - (lane << 2);            // 128-aligned window base
    unsigned zeros = (~m) & 0xFu;
    int lz = zeros ? (base + 31 - __clz(zeros)) : (wbase - 1);

    int incl = lz;
    #pragma unroll
    for (int off = 1; off < 32; off <<= 1) {
        int t = __shfl_up_sync(0xffffffffu, incl, off);
        if (lane >= off) incl = max(incl, t);
    }
    int excl = __shfl_up_sync(0xffffffffu, incl, 1);
    if (lane == 0) excl = wbase - 1;

    int p[4];
    int prevz = excl;
    #pragma unroll
    for (int j = 0; j < 4; j++) {
        int i = base + j;
        if ((m >> j) & 1u) {
            int pj = prevz + 1;
            if (i == wbase && (i & (E - 1)) != 0 && x[i - 1] > 0.0f) pj = i - 1;
            p[j] = pj;
        } else {
            p[j] = i;
            prevz = i;
        }
    }
    reinterpret_cast<int4*>(g_parent)[chunk] = make_int4(p[0], p[1], p[2], p[3]);
    reinterpret_cast<float4*>(g_sum)[chunk]  = make_float4(0.f, 0.f, 0.f, 0.f);
    reinterpret_cast<int4*>(g_cnt)[chunk]    = make_int4(0, 0, 0, 0);

    __syncthreads();
    if (threadIdx.x < 32) {
        unsigned w = 0;
        #pragma unroll
        for (int k = 0; k < 8; k++)
            w |= (unsigned)s_nib[threadIdx.x * 8 + k] << (4 * k);
        g_mask[blockIdx.x * 32 + threadIdx.x] = w;
    }
    if (chunk == 0) { g_total = 0.0; g_ncomp = 0.0; g_done = 0u; }
}

// Vertical unions from mask words: one block per row (rows 1..E-1),
// one 32-pixel word per thread. Union once per overlap-run start.
__global__ void __launch_bounds__(WPR) k_merge() {
    int row  = blockIdx.x + 1;
    int wcol = threadIdx.x;
    int widx = row * WPR + wcol;
    unsigned wc = g_mask[widx];
    unsigned wu = g_mask[widx - WPR];
    unsigned ov = wc & wu;
    if (!ov) return;

    int lane = threadIdx.x & 31;
    unsigned cl = __shfl_up_sync(0xffffffffu, wc, 1);
    unsigned ul = __shfl_up_sync(0xffffffffu, wu, 1);
    unsigned carry = 0;
    if (wcol > 0) {
        if (lane == 0) {
            cl = g_mask[widx - 1];
            ul = g_mask[widx - 1 - WPR];
        }
        carry = (cl >> 31) & (ul >> 31) & 1u;
    }
    unsigned starts = ov & ~((ov << 1) | carry);

    int base = row * E + (wcol << 5);
    while (starts) {
        int b = __ffs(starts) - 1;
        starts &= starts - 1;
        unite(base + b, base + b - E);
    }
}

// One find + two non-returning atomics per horizontal run.
__global__ void k_accum(const float* __restrict__ x) {
    int chunk = blockIdx.x * blockDim.x + threadIdx.x;
    int base  = chunk << 2;
    float4 xv = reinterpret_cast<const float4*>(x)[chunk];
    float v[4] = {xv.x, xv.y, xv.z, xv.w};
    int lane    = threadIdx.x & 31;
    float lw    = __shfl_up_sync(0xffffffffu, xv.w, 1);
    int colbase = base & (E - 1);
    float left0;
    if (colbase == 0)   left0 = -1.0f;
    else if (lane > 0)  left0 = lw;
    else                left0 = x[base - 1];

    #pragma unroll
    for (int j = 0; j < 4; j++) {
        float lv = j ? v[j-1] : left0;
        if (v[j] > 0.0f && lv <= 0.0f) {
            int   i   = base + j;
            int   col = colbase + j;
            float s   = 0.0f;
            int   len = 0;
            float cur = v[j];
            while (true) {
                s += tanh_pos(cur);
                len++;
                if (col + len >= E) break;
                cur = (j + len < 4) ? v[j + len] : x[i + len];
                if (cur <= 0.0f) break;
            }
            int r = find_root(i);
            atomicAdd(&g_sum[r], s);
            atomicAdd(&g_cnt[r], len);
        }
    }
}

// Cnt-gated vectorized scan; block-reduce; last block writes the output.
__global__ void k_final(float* __restrict__ out) {
    int chunk = blockIdx.x * blockDim.x + threadIdx.x;
    const float np1 = (float)(NPIX + 1);
    double t = 0.0, c = 0.0;
    int4 cn = reinterpret_cast<const int4*>(g_cnt)[chunk];
    if (cn.x | cn.y | cn.z | cn.w) {
        float4 sv = reinterpret_cast<const float4*>(g_sum)[chunk];
        int   cc[4] = {cn.x, cn.y, cn.z, cn.w};
        float ss[4] = {sv.x, sv.y, sv.z, sv.w};
        #pragma unroll
        for (int j = 0; j < 4; j++) {
            if (cc[j] > 0) {
                float denom = np1 - (float)cc[j];   // fp32 like reference
                t += (double)(ss[j] / denom);
                c += 1.0;
            }
        }
    }
    #pragma unroll
    for (int off = 16; off; off >>= 1) {
        t += __shfl_down_sync(0xffffffffu, t, off);
        c += __shfl_down_sync(0xffffffffu, c, off);
    }
    __shared__ double st[8], sc[8];
    int lane = threadIdx.x & 31;
    int w    = threadIdx.x >> 5;
    if (lane == 0) { st[w] = t; sc[w] = c; }
    __syncthreads();
    if (w == 0) {
        int nw = blockDim.x >> 5;
        t = (lane < nw) ? st[lane] : 0.0;
        c = (lane < nw) ? sc[lane] : 0.0;
        #pragma unroll
        for (int off = 4; off; off >>= 1) {
            t += __shfl_down_sync(0xffffffffu, t, off);
            c += __shfl_down_sync(0xffffffffu, c, off);
        }
        if (lane == 0) {
            atomicAdd(&g_total, t);
            atomicAdd(&g_ncomp, c);
            __threadfence();
            unsigned ticket = atomicAdd(&g_done, 1u);
            if (ticket == gridDim.x - 1) {
                double tt = *((volatile double*)&g_total);
                double nc = *((volatile double*)&g_ncomp);
                out[0] = (nc > 0.0) ? (float)(tt / nc) : 0.0f;
            }
        }
    }
}

extern "C" void kernel_launch(void* const* d_in, const int* in_sizes, int n_in,
                              void* d_out, int out_size) {
    const float* x   = (const float*)d_in[0];
    float*       out = (float*)d_out;

    const int threads    = 256;
    const int chunks_all = NPIX / 4;

    k_init <<<chunks_all / threads, threads>>>(x);
    k_merge<<<E - 1, WPR>>>();
    k_accum<<<chunks_all / threads, threads>>>(x);
    k_final<<<chunks_all / threads, threads>>>(out);
}

// round 9
// speedup vs baseline: 3.6308x; 1.0527x over previous
#include <cuda_runtime.h>

// LossMIDU: mean over 4-connected components of the tanh(x)>0 mask of
//   sum(tanh(x) in comp) / (N+1 - count(comp)).
// Run-based union-find CCL, bitmask merge, packed float2 accumulator:
//   k_init : parent[i] = horizontal run start (warp scan) + mask bits
//   k_merge: vertical CAS unions from mask words, one per overlap-run start
//   k_accum: one find + ONE float2 vector atomic per horizontal run
//   k_final: scan packed acc, reduce, zero consumed entries, write out

static constexpr int E      = 4096;
static constexpr int NPIX   = E * E;
static constexpr int WORDS  = NPIX / 32;
static constexpr int WPR    = E / 32;          // words per row = 128

__device__ int      g_parent[NPIX];
__device__ float4   g_acc4[NPIX / 2];          // interleaved (sum, cnt) pairs
__device__ unsigned g_mask[WORDS];
__device__ double   g_total;
__device__ double   g_ncomp;
__device__ unsigned g_done;

// tanh for v > 0 via MUFU: tanh(v) = (1 - e)/(1 + e), e = exp(-2v).
// Verified rel_err 0.0 vs reference in rounds 5/7.
__device__ __forceinline__ float tanh_pos(float v) {
    float e = __expf(-2.0f * v);               // (0, 1]
    return __fdividef(1.0f - e, 1.0f + e);
}

// Path-halving find. Links always point to strictly smaller indices.
__device__ __forceinline__ int find_root(int i) {
    int p = g_parent[i];
    if (p == i) return i;
    while (true) {
        int gp = g_parent[p];
        if (gp == p) return p;
        g_parent[i] = gp;   // path halving (monotone toward root, race-safe)
        i = p;
        p = gp;
    }
}

__device__ __forceinline__ void unite(int a, int b) {
    int ra = find_root(a);
    int rb = find_root(b);
    while (ra != rb) {
        if (ra > rb) { int t = ra; ra = rb; rb = t; }
        int old = atomicCAS(&g_parent[rb], rb, ra);
        if (old == rb) return;
        rb = find_root(old);
    }
}

// parent[i] = horizontal run start via warp max-scan over 128-pixel windows
// (windows never span rows). Also emits the bitmask. Does NOT touch g_acc4:
// accumulator entries are zeroed lazily by k_final after consumption.
__global__ void k_init(const float* __restrict__ x) {
    int chunk = blockIdx.x * blockDim.x + threadIdx.x;
    int base  = chunk << 2;
    float4 xv = reinterpret_cast<const float4*>(x)[chunk];
    float v[4] = {xv.x, xv.y, xv.z, xv.w};
    unsigned m = 0;
    #pragma unroll
    for (int j = 0; j < 4; j++) m |= (unsigned)(v[j] > 0.0f) << j;

    __shared__ unsigned char s_nib[256];
    s_nib[threadIdx.x] = (unsigned char)m;

    int lane  = threadIdx.x & 31;
    int wbase = base - (lane << 2);            // 128-aligned window base
    unsigned zeros = (~m) & 0xFu;
    int lz = zeros ? (base + 31 - __clz(zeros)) : (wbase - 1);

    int incl = lz;
    #pragma unroll
    for (int off = 1; off < 32; off <<= 1) {
        int t = __shfl_up_sync(0xffffffffu, incl, off);
        if (lane >= off) incl = max(incl, t);
    }
    int excl = __shfl_up_sync(0xffffffffu, incl, 1);
    if (lane == 0) excl = wbase - 1;

    int p[4];
    int prevz = excl;
    #pragma unroll
    for (int j = 0; j < 4; j++) {
        int i = base + j;
        if ((m >> j) & 1u) {
            int pj = prevz + 1;
            if (i == wbase && (i & (E - 1)) != 0 && x[i - 1] > 0.0f) pj = i - 1;
            p[j] = pj;
        } else {
            p[j] = i;
            prevz = i;
        }
    }
    reinterpret_cast<int4*>(g_parent)[chunk] = make_int4(p[0], p[1], p[2], p[3]);

    __syncthreads();
    if (threadIdx.x < 32) {
        unsigned w = 0;
        #pragma unroll
        for (int k = 0; k < 8; k++)
            w |= (unsigned)s_nib[threadIdx.x * 8 + k] << (4 * k);
        g_mask[blockIdx.x * 32 + threadIdx.x] = w;
    }
    if (chunk == 0) { g_total = 0.0; g_ncomp = 0.0; g_done = 0u; }
}

// Vertical unions from mask words: one block per row (rows 1..E-1),
// one 32-pixel word per thread. Union once per overlap-run start.
__global__ void __launch_bounds__(WPR) k_merge() {
    int row  = blockIdx.x + 1;
    int wcol = threadIdx.x;
    int widx = row * WPR + wcol;
    unsigned wc = g_mask[widx];
    unsigned wu = g_mask[widx - WPR];
    unsigned ov = wc & wu;
    if (!ov) return;

    int lane = threadIdx.x & 31;
    unsigned cl = __shfl_up_sync(0xffffffffu, wc, 1);
    unsigned ul = __shfl_up_sync(0xffffffffu, wu, 1);
    unsigned carry = 0;
    if (wcol > 0) {
        if (lane == 0) {
            cl = g_mask[widx - 1];
            ul = g_mask[widx - 1 - WPR];
        }
        carry = (cl >> 31) & (ul >> 31) & 1u;
    }
    unsigned starts = ov & ~((ov << 1) | carry);

    int base = row * E + (wcol << 5);
    while (starts) {
        int b = __ffs(starts) - 1;
        starts &= starts - 1;
        unite(base + b, base + b - E);
    }
}

// One find + one float2 vector atomic per horizontal run.
__global__ void k_accum(const float* __restrict__ x) {
    int chunk = blockIdx.x * blockDim.x + threadIdx.x;
    int base  = chunk << 2;
    float4 xv = reinterpret_cast<const float4*>(x)[chunk];
    float v[4] = {xv.x, xv.y, xv.z, xv.w};
    int lane    = threadIdx.x & 31;
    float lw    = __shfl_up_sync(0xffffffffu, xv.w, 1);
    int colbase = base & (E - 1);
    float left0;
    if (colbase == 0)   left0 = -1.0f;
    else if (lane > 0)  left0 = lw;
    else                left0 = x[base - 1];

    float2* acc2 = reinterpret_cast<float2*>(g_acc4);

    #pragma unroll
    for (int j = 0; j < 4; j++) {
        float lv = j ? v[j-1] : left0;
        if (v[j] > 0.0f && lv <= 0.0f) {
            int   i   = base + j;
            int   col = colbase + j;
            float s   = 0.0f;
            int   len = 0;
            float cur = v[j];
            while (true) {
                s += tanh_pos(cur);
                len++;
                if (col + len >= E) break;
                cur = (j + len < 4) ? v[j + len] : x[i + len];
                if (cur <= 0.0f) break;
            }
            int r = find_root(i);
            atomicAdd(acc2 + r, make_float2(s, (float)len));  // sm_90+ vector red
        }
    }
}

// Scan packed accumulator; reduce; zero consumed entries (lazy re-init for the
// next replay); last block writes the output.
__global__ void k_final(float* __restrict__ out) {
    int chunk = blockIdx.x * blockDim.x + threadIdx.x;   // 4 entries = 2 float4
    const float np1 = (float)(NPIX + 1);
    double t = 0.0, c = 0.0;
    const float4 z4 = make_float4(0.f, 0.f, 0.f, 0.f);

    #pragma unroll
    for (int h = 0; h < 2; h++) {
        int    idx = chunk * 2 + h;
        float4 a   = g_acc4[idx];
        if (a.y != 0.0f || a.w != 0.0f) {
            if (a.y != 0.0f) { t += (double)(a.x / (np1 - a.y)); c += 1.0; }
            if (a.w != 0.0f) { t += (double)(a.z / (np1 - a.w)); c += 1.0; }
            g_acc4[idx] = z4;          // lazy zero for next replay
        }
    }

    #pragma unroll
    for (int off = 16; off; off >>= 1) {
        t += __shfl_down_sync(0xffffffffu, t, off);
        c += __shfl_down_sync(0xffffffffu, c, off);
    }
    __shared__ double st[8], sc[8];
    int lane = threadIdx.x & 31;
    int w    = threadIdx.x >> 5;
    if (lane == 0) { st[w] = t; sc[w] = c; }
    __syncthreads();
    if (w == 0) {
        int nw = blockDim.x >> 5;
        t = (lane < nw) ? st[lane] : 0.0;
        c = (lane < nw) ? sc[lane] : 0.0;
        #pragma unroll
        for (int off = 4; off; off >>= 1) {
            t += __shfl_down_sync(0xffffffffu, t, off);
            c += __shfl_down_sync(0xffffffffu, c, off);
        }
        if (lane == 0) {
            atomicAdd(&g_total, t);
            atomicAdd(&g_ncomp, c);
            __threadfence();
            unsigned ticket = atomicAdd(&g_done, 1u);
            if (ticket == gridDim.x - 1) {
                double tt = *((volatile double*)&g_total);
                double nc = *((volatile double*)&g_ncomp);
                out[0] = (nc > 0.0) ? (float)(tt / nc) : 0.0f;
            }
        }
    }
}

extern "C" void kernel_launch(void* const* d_in, const int* in_sizes, int n_in,
                              void* d_out, int out_size) {
    const float* x   = (const float*)d_in[0];
    float*       out = (float*)d_out;

    const int threads    = 256;
    const int chunks_all = NPIX / 4;

    k_init <<<chunks_all / threads, threads>>>(x);
    k_merge<<<E - 1, WPR>>>();
    k_accum<<<chunks_all / threads, threads>>>(x);
    k_final<<<chunks_all / threads, threads>>>(out);
}